// round 2
// baseline (speedup 1.0000x reference)
#include <cuda_runtime.h>
#include <math.h>
#include <float.h>

#define NOFF 20
#define NSMALL 13            // offsets <= 16 served from the smem window
#define WIN   80             // rows [n0-16, n0+64)
#define HDIM 128
#define SEQN 8192
#define NH   16
#define NB   2
#define WARPS 8
#define QPW   8              // queries per warp
#define QPB  (WARPS * QPW)   // 64 queries per block

__constant__ int c_offs[NOFF] = {1,2,3,4,5,6,7,8,9,11,13,15,16,23,32,64,128,256,512,1024};

// ---- packed f32x2 helpers ----
__device__ __forceinline__ unsigned long long f2add(unsigned long long a, unsigned long long b) {
    unsigned long long d;
    asm("add.rn.f32x2 %0, %1, %2;" : "=l"(d) : "l"(a), "l"(b));
    return d;
}
__device__ __forceinline__ unsigned long long f2fma(unsigned long long a, unsigned long long b, unsigned long long c) {
    unsigned long long d;
    asm("fma.rn.f32x2 %0, %1, %2, %3;" : "=l"(d) : "l"(a), "l"(b), "l"(c));
    return d;
}
__device__ __forceinline__ float2 f2unpack(unsigned long long a) {
    float lo, hi;
    asm("mov.b64 {%0, %1}, %2;" : "=f"(lo), "=f"(hi) : "l"(a));
    return make_float2(lo, hi);
}
__device__ __forceinline__ unsigned long long f2bcast(float x) {
    unsigned long long d;
    asm("mov.b64 %0, {%1, %1};" : "=l"(d) : "f"(x));
    return d;
}

__global__ void __launch_bounds__(256) dsqg_fwd(
    const float* __restrict__ q, const float* __restrict__ k, const float* __restrict__ v,
    const float* __restrict__ pb, const float* __restrict__ se, float* __restrict__ out)
{
    constexpr int offs[NOFF] = {1,2,3,4,5,6,7,8,9,11,13,15,16,23,32,64,128,256,512,1024};

    extern __shared__ float win[];              // kwin[WIN*HDIM] | vwin[WIN*HDIM]  (80KB dynamic)
    float* kwin = win;
    float* vwin = win + WIN * HDIM;

    __shared__ float se_s[NOFF * HDIM];         // scale_embed
    __shared__ float pb_s[NOFF];                // pos_bias column for this head
    __shared__ float red_s[WARPS][32][21];      // conflict-free transpose reduce

    const int tid = threadIdx.x;
    const int w   = tid >> 5;
    const int l   = tid & 31;

    const int bid = blockIdx.x;
    const int bh  = bid >> 7;                    // 128 blocks per (b,h)
    const int n0  = (bid & 127) * QPB;           // 64 queries per block
    const int h   = bh & (NH - 1);

    const size_t base = (size_t)bh * SEQN * HDIM;
    const float* kb = k + base;
    const float* vb = v + base;

    // stage scale_embed + pos_bias
    for (int i = tid; i < NOFF * HDIM / 4; i += 256)
        ((float4*)se_s)[i] = ((const float4*)se)[i];
    if (tid < NOFF) pb_s[tid] = pb[tid * NH + h];

    // preload k/v window rows [n0-16, n0+64) (clamped; clamped rows are masked later)
    for (int i = tid; i < WIN * 32; i += 256) {
        const int row = i >> 5, c = i & 31;
        int g = n0 - 16 + row; if (g < 0) g = 0;
        ((float4*)kwin)[i] = ((const float4*)(kb + (size_t)g * HDIM))[c];
        ((float4*)vwin)[i] = ((const float4*)(vb + (size_t)g * HDIM))[c];
    }
    __syncthreads();

    const float sc = 0.088388347648318447f;     // 1/sqrt(128)
    const int d4 = l * 4;

    for (int it = 0; it < QPW; ++it) {
        const int n    = n0 + it * WARPS + w;   // adjacent warps -> adjacent queries
        const int nrel = it * WARPS + w + 16;   // window-relative row of query n
        const ulonglong2 qq = *(const ulonglong2*)(q + base + (size_t)n * HDIM + d4);

        unsigned long long acc[NOFF];
#pragma unroll
        for (int j = 0; j < NOFF; ++j) acc[j] = 0ULL;

        // ---- small offsets: k from smem window ----
#pragma unroll
        for (int j = 0; j < NSMALL; ++j) {
            const float* kr = kwin + (nrel - offs[j]) * HDIM + d4;
            const ulonglong2 kk = *(const ulonglong2*)kr;
            const ulonglong2 sj = *(const ulonglong2*)(se_s + j * HDIM + d4);
            acc[j] = f2fma(qq.x, f2add(kk.x, sj.x), acc[j]);
            acc[j] = f2fma(qq.y, f2add(kk.y, sj.y), acc[j]);
        }
        // ---- large offsets: k from global ----
#pragma unroll
        for (int j = NSMALL; j < NOFF; ++j) {
            int kp = n - offs[j]; if (kp < 0) kp = 0;
            const ulonglong2 kk = *(const ulonglong2*)(kb + (size_t)kp * HDIM + d4);
            const ulonglong2 sj = *(const ulonglong2*)(se_s + j * HDIM + d4);
            acc[j] = f2fma(qq.x, f2add(kk.x, sj.x), acc[j]);
            acc[j] = f2fma(qq.y, f2add(kk.y, sj.y), acc[j]);
        }

        // ---- warp reduce via smem transpose ----
#pragma unroll
        for (int j = 0; j < NOFF; ++j) {
            float2 t = f2unpack(acc[j]);
            red_s[w][l][j] = t.x + t.y;
        }
        __syncwarp();

        float s = -FLT_MAX;
        bool valid = false;
        if (l < NOFF) {
            float t = 0.f;
#pragma unroll
            for (int i = 0; i < 32; ++i) t += red_s[w][i][l];
            valid = (n - c_offs[l] >= 0);
            if (valid) s = t * sc + pb_s[l];
        }
        __syncwarp();   // red_s safe to reuse next iteration

        // ---- lane-distributed softmax over 20 offsets ----
        float m = s;
#pragma unroll
        for (int o = 16; o; o >>= 1) m = fmaxf(m, __shfl_xor_sync(0xffffffffu, m, o));
        float e = valid ? __expf(s - m) : 0.f;
        float lsum = e;
#pragma unroll
        for (int o = 16; o; o >>= 1) lsum += __shfl_xor_sync(0xffffffffu, lsum, o);
        const float pval = e * (lsum > 0.f ? 1.f / lsum : 0.f);   // n=0 row -> all p=0 -> out=0

        // ---- output: small offsets from smem window, large from global ----
        unsigned long long o01 = 0ULL, o23 = 0ULL;
#pragma unroll
        for (int j = 0; j < NSMALL; ++j) {
            const float* vr = vwin + (nrel - offs[j]) * HDIM + d4;
            const ulonglong2 vv = *(const ulonglong2*)vr;
            const unsigned long long pp = f2bcast(__shfl_sync(0xffffffffu, pval, j));
            o01 = f2fma(pp, vv.x, o01);
            o23 = f2fma(pp, vv.y, o23);
        }
#pragma unroll
        for (int j = NSMALL; j < NOFF; ++j) {
            int kp = n - offs[j]; if (kp < 0) kp = 0;
            const ulonglong2 vv = *(const ulonglong2*)(vb + (size_t)kp * HDIM + d4);
            const unsigned long long pp = f2bcast(__shfl_sync(0xffffffffu, pval, j));
            o01 = f2fma(pp, vv.x, o01);
            o23 = f2fma(pp, vv.y, o23);
        }
        float2 a = f2unpack(o01), b2 = f2unpack(o23);
        *(float4*)(out + base + (size_t)n * HDIM + d4) = make_float4(a.x, a.y, b2.x, b2.y);
    }
}

extern "C" void kernel_launch(void* const* d_in, const int* in_sizes, int n_in,
                              void* d_out, int out_size) {
    const float* q  = (const float*)d_in[0];
    const float* k  = (const float*)d_in[1];
    const float* v  = (const float*)d_in[2];
    const float* pb = (const float*)d_in[3];
    const float* se = (const float*)d_in[4];
    (void)in_sizes; (void)n_in; (void)out_size;

    const int dyn_smem = 2 * WIN * HDIM * (int)sizeof(float);   // 80 KB
    static bool attr_set = false;   // idempotent host-side attribute; same work every call
    if (!attr_set) {
        cudaFuncSetAttribute(dsqg_fwd, cudaFuncAttributeMaxDynamicSharedMemorySize, dyn_smem);
        attr_set = true;
    }
    dsqg_fwd<<<NB * NH * (SEQN / QPB), 256, dyn_smem>>>(q, k, v, pb, se, (float*)d_out);
}

// round 3
// speedup vs baseline: 1.1266x; 1.1266x over previous
#include <cuda_runtime.h>
#include <cuda_fp16.h>
#include <math.h>
#include <float.h>

#define NOFF 20
#define HDIM 128
#define SEQN 8192
#define NH   16
#define NB   2
#define WARPS 8
#define QPW   8              // queries per warp
#define QPB  (WARPS * QPW)   // 64 queries per block

__constant__ int c_offs[NOFF] = {1,2,3,4,5,6,7,8,9,11,13,15,16,23,32,64,128,256,512,1024};

// ---- packed f32x2 helpers ----
__device__ __forceinline__ unsigned long long f2fma(unsigned long long a, unsigned long long b, unsigned long long c) {
    unsigned long long d;
    asm("fma.rn.f32x2 %0, %1, %2, %3;" : "=l"(d) : "l"(a), "l"(b), "l"(c));
    return d;
}
__device__ __forceinline__ unsigned long long f2add(unsigned long long a, unsigned long long b) {
    unsigned long long d;
    asm("add.rn.f32x2 %0, %1, %2;" : "=l"(d) : "l"(a), "l"(b));
    return d;
}
__device__ __forceinline__ float2 f2unpack(unsigned long long a) {
    float lo, hi;
    asm("mov.b64 {%0, %1}, %2;" : "=f"(lo), "=f"(hi) : "l"(a));
    return make_float2(lo, hi);
}
__device__ __forceinline__ unsigned long long f2pack(float lo, float hi) {
    unsigned long long d;
    asm("mov.b64 %0, {%1, %2};" : "=l"(d) : "f"(lo), "f"(hi));
    return d;
}
__device__ __forceinline__ unsigned long long f2bcast(float x) {
    unsigned long long d;
    asm("mov.b64 %0, {%1, %1};" : "=l"(d) : "f"(x));
    return d;
}

__global__ void __launch_bounds__(256, 4) dsqg_fwd(
    const float* __restrict__ q, const float* __restrict__ k, const float* __restrict__ v,
    const float* __restrict__ pb, const float* __restrict__ se, float* __restrict__ out)
{
    constexpr int offs[NOFF] = {1,2,3,4,5,6,7,8,9,11,13,15,16,23,32,64,128,256,512,1024};

    __shared__ __align__(16) __half2 se_h[NOFF * HDIM / 2];   // fp16 scale_embed (5KB)
    __shared__ unsigned long long red2[WARPS][8][10];         // narrow transpose reduce (5KB)
    __shared__ float pb_s[NOFF];

    const int tid = threadIdx.x;
    const int w   = tid >> 5;
    const int l   = tid & 31;

    const int bid = blockIdx.x;
    const int bh  = bid >> 7;                    // 128 blocks per (b,h)
    const int n0  = (bid & 127) * QPB;
    const int h   = bh & (NH - 1);

    // stage fp16 scale_embed + pos_bias
    for (int i = tid; i < NOFF * HDIM / 2; i += 256) {
        float2 f = ((const float2*)se)[i];
        se_h[i] = __float22half2_rn(f);
    }
    if (tid < NOFF) pb_s[tid] = pb[tid * NH + h];
    __syncthreads();

    const float sc = 0.088388347648318447f;      // 1/sqrt(128)
    const size_t base = (size_t)bh * SEQN * HDIM;
    const float* kb = k + base;
    const float* vb = v + base;
    const int d4 = l * 4;

    for (int it = 0; it < QPW; ++it) {
        const int n = n0 + it * WARPS + w;       // adjacent warps -> adjacent queries
        const float4 qq = *(const float4*)(q + base + (size_t)n * HDIM + d4);

        // ---- scores: q . (k[n-dj] + se_j), scalar accumulators (reg pressure) ----
        float acc[NOFF];
#pragma unroll
        for (int j = 0; j < NOFF; ++j) {
            int kp = n - offs[j]; if (kp < 0) kp = 0;
            const float4 kk = *(const float4*)(kb + (size_t)kp * HDIM + d4);
            const uint2 sh = *(const uint2*)(se_h + j * (HDIM / 2) + 2 * l);  // 4 halfs
            const float2 s01 = __half22float2(*(const __half2*)&sh.x);
            const float2 s23 = __half22float2(*(const __half2*)&sh.y);
            acc[j] = fmaf(qq.x, kk.x + s01.x,
                     fmaf(qq.y, kk.y + s01.y,
                     fmaf(qq.z, kk.z + s23.x,
                          qq.w * (kk.w + s23.y))));
        }

        // ---- reduce: 2 shfl rounds (off L1tex pipe) + narrow smem transpose ----
        unsigned long long u[10];
#pragma unroll
        for (int m = 0; m < 10; ++m) u[m] = f2pack(acc[2 * m], acc[2 * m + 1]);
#pragma unroll
        for (int m = 0; m < 10; ++m) u[m] = f2add(u[m], __shfl_xor_sync(0xffffffffu, u[m], 16));
#pragma unroll
        for (int m = 0; m < 10; ++m) u[m] = f2add(u[m], __shfl_xor_sync(0xffffffffu, u[m], 8));
        if (l < 8) {
#pragma unroll
            for (int m = 0; m < 10; ++m) red2[w][l][m] = u[m];
        }
        __syncwarp();

        float s = -FLT_MAX;
        bool valid = false;
        {
            const int m = (l < NOFF ? l : 0) >> 1;
            unsigned long long t = 0ULL;
#pragma unroll
            for (int i = 0; i < 8; ++i) t = f2add(t, red2[w][i][m]);
            float2 tp = f2unpack(t);
            const float tj = (l & 1) ? tp.y : tp.x;
            if (l < NOFF) {
                valid = (n - c_offs[l] >= 0);
                if (valid) s = tj * sc + pb_s[l];
            }
        }
        __syncwarp();   // red2 safe for next iteration

        // ---- lane-distributed softmax over 20 offsets ----
        float m = s;
#pragma unroll
        for (int o = 16; o; o >>= 1) m = fmaxf(m, __shfl_xor_sync(0xffffffffu, m, o));
        float e = valid ? __expf(s - m) : 0.f;
        float lsum = e;
#pragma unroll
        for (int o = 16; o; o >>= 1) lsum += __shfl_xor_sync(0xffffffffu, lsum, o);
        const float pval = e * (lsum > 0.f ? 1.f / lsum : 0.f);   // n=0 -> all p=0 -> out=0

        // ---- output: sum_j p_j * v[n-dj], packed f32x2 ----
        unsigned long long o01 = 0ULL, o23 = 0ULL;
#pragma unroll
        for (int j = 0; j < NOFF; ++j) {
            int kp = n - offs[j]; if (kp < 0) kp = 0;
            const ulonglong2 vv = *(const ulonglong2*)(vb + (size_t)kp * HDIM + d4);
            const unsigned long long pp = f2bcast(__shfl_sync(0xffffffffu, pval, j));
            o01 = f2fma(pp, vv.x, o01);
            o23 = f2fma(pp, vv.y, o23);
        }
        float2 a = f2unpack(o01), b2 = f2unpack(o23);
        *(float4*)(out + base + (size_t)n * HDIM + d4) = make_float4(a.x, a.y, b2.x, b2.y);
    }
}

extern "C" void kernel_launch(void* const* d_in, const int* in_sizes, int n_in,
                              void* d_out, int out_size) {
    const float* q  = (const float*)d_in[0];
    const float* k  = (const float*)d_in[1];
    const float* v  = (const float*)d_in[2];
    const float* pb = (const float*)d_in[3];
    const float* se = (const float*)d_in[4];
    (void)in_sizes; (void)n_in; (void)out_size;
    dsqg_fwd<<<NB * NH * (SEQN / QPB), 256>>>(q, k, v, pb, se, (float*)d_out);
}

// round 6
// speedup vs baseline: 1.3084x; 1.1614x over previous
#include <cuda_runtime.h>
#include <cuda_fp16.h>
#include <math.h>
#include <float.h>

#define NOFF 20
#define HDIM 128
#define SEQN 8192
#define NH   16
#define NB   2
#define WARPS 8
#define QPW   8
#define QPB  (WARPS * QPW)            // 64 queries per block
#define TOTE (NB * NH * SEQN * HDIM)  // 33554432 elements

__constant__ int c_offs[NOFF] = {1,2,3,4,5,6,7,8,9,11,13,15,16,23,32,64,128,256,512,1024};

// fp16 mirrors of k and v (static device scratch; allocation-free)
__device__ __half g_kh[TOTE];
__device__ __half g_vh[TOTE];

__device__ __forceinline__ unsigned long long f2add(unsigned long long a, unsigned long long b) {
    unsigned long long d;
    asm("add.rn.f32x2 %0, %1, %2;" : "=l"(d) : "l"(a), "l"(b));
    return d;
}
__device__ __forceinline__ unsigned long long f2pack(float lo, float hi) {
    unsigned long long d;
    asm("mov.b64 %0, {%1, %2};" : "=l"(d) : "f"(lo), "f"(hi));
    return d;
}
__device__ __forceinline__ float2 f2unpack(unsigned long long a) {
    float lo, hi;
    asm("mov.b64 {%0, %1}, %2;" : "=f"(lo), "=f"(hi) : "l"(a));
    return make_float2(lo, hi);
}
__device__ __forceinline__ unsigned int h2u(__half2 h) {
    union { __half2 h; unsigned int u; } c; c.h = h; return c.u;
}

// ---- pre-pass: fp32 k,v -> fp16 mirrors (pure streaming) ----
__global__ void __launch_bounds__(256) cvt_kv(const float* __restrict__ k, const float* __restrict__ v)
{
    const int total4 = TOTE / 4;
    for (int i = blockIdx.x * blockDim.x + threadIdx.x; i < total4; i += gridDim.x * blockDim.x) {
        float4 a = ((const float4*)k)[i];
        uint2 ka;
        ka.x = h2u(__floats2half2_rn(a.x, a.y));
        ka.y = h2u(__floats2half2_rn(a.z, a.w));
        ((uint2*)g_kh)[i] = ka;
        float4 b = ((const float4*)v)[i];
        uint2 vb2;
        vb2.x = h2u(__floats2half2_rn(b.x, b.y));
        vb2.y = h2u(__floats2half2_rn(b.z, b.w));
        ((uint2*)g_vh)[i] = vb2;
    }
}

__global__ void __launch_bounds__(256) dsqg_fwd(
    const float* __restrict__ q, const float* __restrict__ pb,
    const float* __restrict__ se, float* __restrict__ out)
{
    constexpr int offs[NOFF] = {1,2,3,4,5,6,7,8,9,11,13,15,16,23,32,64,128,256,512,1024};

    __shared__ __align__(16) __half2 se_h[NOFF * HDIM / 2];   // fp16 scale_embed (5KB)
    __shared__ unsigned long long red2[WARPS][8][10];         // narrow transpose reduce
    __shared__ float pb_s[NOFF];

    const int tid = threadIdx.x;
    const int w   = tid >> 5;
    const int l   = tid & 31;

    const int bid = blockIdx.x;
    const int bh  = bid >> 7;
    const int n0  = (bid & 127) * QPB;
    const int h   = bh & (NH - 1);

    for (int i = tid; i < NOFF * HDIM / 2; i += 256) {
        float2 f = ((const float2*)se)[i];
        se_h[i] = __float22half2_rn(f);
    }
    if (tid < NOFF) pb_s[tid] = pb[tid * NH + h];
    __syncthreads();

    const float sc = 0.088388347648318447f;      // 1/sqrt(128)
    const size_t base = (size_t)bh * SEQN * HDIM;
    const __half* kb = g_kh + base;
    const __half* vb = g_vh + base;
    const int d4 = l * 4;

    for (int it = 0; it < QPW; ++it) {
        const int n = n0 + it * WARPS + w;
        const float4 qq = *(const float4*)(q + base + (size_t)n * HDIM + d4);

        // ---- scores: q . (k16[n-dj] + se16_j), fp32 accumulation ----
        float acc[NOFF];
#pragma unroll
        for (int j = 0; j < NOFF; ++j) {
            int kp = n - offs[j]; if (kp < 0) kp = 0;
            const uint2 kk = *(const uint2*)(kb + (size_t)kp * HDIM + d4);   // 4 halfs
            const uint2 sh = *(const uint2*)(se_h + j * (HDIM / 2) + 2 * l);
            const __half2 a01 = __hadd2(*(const __half2*)&kk.x, *(const __half2*)&sh.x);
            const __half2 a23 = __hadd2(*(const __half2*)&kk.y, *(const __half2*)&sh.y);
            const float2 f01 = __half22float2(a01);
            const float2 f23 = __half22float2(a23);
            acc[j] = fmaf(qq.x, f01.x,
                     fmaf(qq.y, f01.y,
                     fmaf(qq.z, f23.x,
                          qq.w * f23.y)));
        }

        // ---- reduce: 2 shfl rounds + narrow smem transpose ----
        unsigned long long u[10];
#pragma unroll
        for (int m = 0; m < 10; ++m) u[m] = f2pack(acc[2 * m], acc[2 * m + 1]);
#pragma unroll
        for (int m = 0; m < 10; ++m) u[m] = f2add(u[m], __shfl_xor_sync(0xffffffffu, u[m], 16));
#pragma unroll
        for (int m = 0; m < 10; ++m) u[m] = f2add(u[m], __shfl_xor_sync(0xffffffffu, u[m], 8));
        if (l < 8) {
#pragma unroll
            for (int m = 0; m < 10; ++m) red2[w][l][m] = u[m];
        }
        __syncwarp();

        float s = -FLT_MAX;
        bool valid = false;
        {
            const int m = (l < NOFF ? l : 0) >> 1;
            unsigned long long t = 0ULL;
#pragma unroll
            for (int i = 0; i < 8; ++i) t = f2add(t, red2[w][i][m]);
            float2 tp = f2unpack(t);
            const float tj = (l & 1) ? tp.y : tp.x;
            if (l < NOFF) {
                valid = (n - c_offs[l] >= 0);
                if (valid) s = tj * sc + pb_s[l];
            }
        }
        __syncwarp();

        // ---- lane-distributed softmax over 20 offsets ----
        float m = s;
#pragma unroll
        for (int o = 16; o; o >>= 1) m = fmaxf(m, __shfl_xor_sync(0xffffffffu, m, o));
        float e = valid ? __expf(s - m) : 0.f;
        float lsum = e;
#pragma unroll
        for (int o = 16; o; o >>= 1) lsum += __shfl_xor_sync(0xffffffffu, lsum, o);
        const float pval = e * (lsum > 0.f ? 1.f / lsum : 0.f);   // n=0 -> p=0 -> out=0

        // ---- output: sum_j p_j * v16[n-dj] ----
        float o0 = 0.f, o1 = 0.f, o2 = 0.f, o3 = 0.f;
#pragma unroll
        for (int j = 0; j < NOFF; ++j) {
            int kp = n - offs[j]; if (kp < 0) kp = 0;
            const uint2 vv = *(const uint2*)(vb + (size_t)kp * HDIM + d4);
            const float2 f01 = __half22float2(*(const __half2*)&vv.x);
            const float2 f23 = __half22float2(*(const __half2*)&vv.y);
            const float pp = __shfl_sync(0xffffffffu, pval, j);
            o0 = fmaf(pp, f01.x, o0);
            o1 = fmaf(pp, f01.y, o1);
            o2 = fmaf(pp, f23.x, o2);
            o3 = fmaf(pp, f23.y, o3);
        }
        *(float4*)(out + base + (size_t)n * HDIM + d4) = make_float4(o0, o1, o2, o3);
    }
}

extern "C" void kernel_launch(void* const* d_in, const int* in_sizes, int n_in,
                              void* d_out, int out_size) {
    const float* q  = (const float*)d_in[0];
    const float* k  = (const float*)d_in[1];
    const float* v  = (const float*)d_in[2];
    const float* pb = (const float*)d_in[3];
    const float* se = (const float*)d_in[4];
    (void)in_sizes; (void)n_in; (void)out_size;

    cvt_kv<<<8192, 256>>>(k, v);                              // fp32 -> fp16 mirrors
    dsqg_fwd<<<NB * NH * (SEQN / QPB), 256>>>(q, pb, se, (float*)d_out);
}